// round 1
// baseline (speedup 1.0000x reference)
#include <cuda_runtime.h>
#include <math.h>

#define BATCH   16384
#define FK      64
#define VISD    2048
#define HID     512
#define NUSERS  1000000
#define VOCAB   (NUSERS + 24 + 2 + 8 + 40)

// Scratch (allocation-free rule: __device__ globals)
__device__ float g_x [BATCH * 384];   // [user|hour|gender|attr|age|vis] per row
__device__ float g_fm[BATCH * 2];     // linear part + 2nd-order
__device__ float g_h1[BATCH * HID];
__device__ float g_h2[BATCH * HID];

// ---------------------------------------------------------------------------
// Kernel 1: embedding gathers, tanh*scale, FM second order, fm_w gather.
// 4 samples per 256-thread block, 64 threads (=FACE_K) per sample.
// ---------------------------------------------------------------------------
__global__ void embed_fm_kernel(
    const int* __restrict__ uid, const int* __restrict__ hour,
    const float* __restrict__ scale,
    const int* __restrict__ gender, const int* __restrict__ age,
    const int* __restrict__ attr,
    const float* __restrict__ user_emb, const float* __restrict__ hour_emb,
    const float* __restrict__ gender_emb, const float* __restrict__ age_emb,
    const float* __restrict__ attr_emb,
    const float* __restrict__ fm_w, const float* __restrict__ fm_b)
{
    int s = threadIdx.x >> 6;        // sample slot 0..3
    int k = threadIdx.x & 63;        // feature dim 0..63
    int b = blockIdx.x * 4 + s;

    int u  = uid[b];
    int h  = hour[b];
    int g  = gender[b];
    int a  = age[b];
    int at = attr[b];
    float sc = scale[b];

    float e0 = user_emb[(long)u * 64 + k];
    float e1 = hour_emb[h * 64 + k];
    float e2 = sc * tanhf(gender_emb[g * 64 + k]);
    float e3 = sc * tanhf(attr_emb[at * 64 + k]);
    float e4 = sc * tanhf(age_emb[a * 64 + k]);

    float* xb = g_x + (long)b * 384;
    xb[      k] = e0;
    xb[ 64 + k] = e1;
    xb[128 + k] = e2;
    xb[192 + k] = e3;
    xb[256 + k] = e4;

    float su = e0 + e1 + e2 + e3 + e4;
    float sq = e0*e0 + e1*e1 + e2*e2 + e3*e3 + e4*e4;
    float so = su * su - sq;

    // reduce over the 64 threads of this sample (2 warps)
    #pragma unroll
    for (int o = 16; o > 0; o >>= 1)
        so += __shfl_down_sync(0xffffffffu, so, o);

    __shared__ float red[4][2];
    if ((k & 31) == 0) red[s][k >> 5] = so;
    __syncthreads();

    if (k == 0) {
        float second = 0.5f * (red[s][0] + red[s][1]);
        long c0 = u;
        long c1 = NUSERS + h;
        long c2 = NUSERS + 24 + g;
        long c3 = NUSERS + 26 + a;        // +24+2
        long c4 = NUSERS + 34 + at;       // +24+2+8
        #pragma unroll
        for (int j = 0; j < 2; j++) {
            const float* w = fm_w + (long)j * VOCAB;
            g_fm[b * 2 + j] =
                w[c0] + w[c1] + w[c2] + w[c3] + w[c4] + fm_b[j] + second;
        }
    }
}

// ---------------------------------------------------------------------------
// Generic tiled fp32 GEMM: C[m, ccol0+n] = A[M,K] @ W[N,K]^T + bias (opt relu)
// BM=BN=64, BK=32, 256 threads, 4x4 register tile / thread.
// Tiles stored transposed+padded in smem; float4 smem reads in mainloop.
// ---------------------------------------------------------------------------
__global__ void gemm_kernel(
    const float* __restrict__ A, int lda,
    const float* __restrict__ W,               // [N, K] row-major
    const float* __restrict__ bias,
    float* __restrict__ C, int ldc, int ccol0,
    int K, int relu)
{
    const int BM = 64, BN = 64, BK = 32;
    __shared__ float As[BK][BM + 4];
    __shared__ float Ws[BK][BN + 4];

    int m0 = blockIdx.y * BM;
    int n0 = blockIdx.x * BN;
    int t  = threadIdx.x;
    int ty = t >> 4;      // 0..15 -> row group
    int tx = t & 15;      // 0..15 -> col group

    float acc[4][4] = {};

    const int VPR = BK / 4;                    // float4 per tile row (=8)
    for (int k0 = 0; k0 < K; k0 += BK) {
        #pragma unroll
        for (int i = t; i < BM * VPR; i += 256) {
            int r = i / VPR, v = i % VPR;
            float4 f = *(const float4*)(A + (long)(m0 + r) * lda + k0 + v * 4);
            As[v*4+0][r] = f.x; As[v*4+1][r] = f.y;
            As[v*4+2][r] = f.z; As[v*4+3][r] = f.w;
        }
        #pragma unroll
        for (int i = t; i < BN * VPR; i += 256) {
            int r = i / VPR, v = i % VPR;
            float4 f = *(const float4*)(W + (long)(n0 + r) * K + k0 + v * 4);
            Ws[v*4+0][r] = f.x; Ws[v*4+1][r] = f.y;
            Ws[v*4+2][r] = f.z; Ws[v*4+3][r] = f.w;
        }
        __syncthreads();

        #pragma unroll
        for (int kk = 0; kk < BK; kk++) {
            float4 av = *(const float4*)&As[kk][ty * 4];
            float4 wv = *(const float4*)&Ws[kk][tx * 4];
            float a[4] = {av.x, av.y, av.z, av.w};
            float w[4] = {wv.x, wv.y, wv.z, wv.w};
            #pragma unroll
            for (int i = 0; i < 4; i++)
                #pragma unroll
                for (int j = 0; j < 4; j++)
                    acc[i][j] = fmaf(a[i], w[j], acc[i][j]);
        }
        __syncthreads();
    }

    #pragma unroll
    for (int i = 0; i < 4; i++) {
        int row = m0 + ty * 4 + i;
        #pragma unroll
        for (int j = 0; j < 4; j++) {
            int col = n0 + tx * 4 + j;
            float v = acc[i][j] + bias[col];
            if (relu) v = fmaxf(v, 0.0f);
            C[(long)row * ldc + ccol0 + col - n0 + (n0)] = v;  // = row*ldc + ccol0 + col
        }
    }
}

// ---------------------------------------------------------------------------
// Kernel 5: logits = fm + h2 @ w3^T + b3 ; softmax over 2 classes.
// One warp per sample, 8 samples per block.
// ---------------------------------------------------------------------------
__global__ void final_kernel(const float* __restrict__ w3,
                             const float* __restrict__ b3,
                             float* __restrict__ out)
{
    __shared__ float w3s[2 * HID];
    int t = threadIdx.x;
    for (int i = t; i < 2 * HID; i += 256) w3s[i] = w3[i];
    __syncthreads();

    int warp = t >> 5, lane = t & 31;
    int b = blockIdx.x * 8 + warp;
    const float* h = g_h2 + (long)b * HID;

    float d0 = 0.f, d1 = 0.f;
    #pragma unroll
    for (int i = lane; i < HID; i += 32) {
        float hv = h[i];
        d0 = fmaf(hv, w3s[i],       d0);
        d1 = fmaf(hv, w3s[HID + i], d1);
    }
    #pragma unroll
    for (int o = 16; o > 0; o >>= 1) {
        d0 += __shfl_down_sync(0xffffffffu, d0, o);
        d1 += __shfl_down_sync(0xffffffffu, d1, o);
    }
    if (lane == 0) {
        float l0 = g_fm[b * 2 + 0] + b3[0] + d0;
        float l1 = g_fm[b * 2 + 1] + b3[1] + d1;
        float m  = fmaxf(l0, l1);
        float e0 = expf(l0 - m), e1 = expf(l1 - m);
        float inv = 1.0f / (e0 + e1);
        out[b * 2 + 0] = e0 * inv;
        out[b * 2 + 1] = e1 * inv;
    }
}

// ---------------------------------------------------------------------------
extern "C" void kernel_launch(void* const* d_in, const int* in_sizes, int n_in,
                              void* d_out, int out_size)
{
    const int*   uid        = (const int*)  d_in[0];
    const int*   hour       = (const int*)  d_in[1];
    const float* visual     = (const float*)d_in[2];
    const float* scale      = (const float*)d_in[3];
    const int*   gender     = (const int*)  d_in[4];
    const int*   age        = (const int*)  d_in[5];
    const int*   attribute  = (const int*)  d_in[6];
    const float* user_emb   = (const float*)d_in[7];
    const float* hour_emb   = (const float*)d_in[8];
    const float* gender_emb = (const float*)d_in[9];
    const float* age_emb    = (const float*)d_in[10];
    const float* attr_emb   = (const float*)d_in[11];
    const float* visu_w     = (const float*)d_in[12];
    const float* visu_b     = (const float*)d_in[13];
    const float* fm_w       = (const float*)d_in[14];
    const float* fm_b       = (const float*)d_in[15];
    const float* w1         = (const float*)d_in[16];
    const float* b1         = (const float*)d_in[17];
    const float* w2         = (const float*)d_in[18];
    const float* b2         = (const float*)d_in[19];
    const float* w3         = (const float*)d_in[20];
    const float* b3         = (const float*)d_in[21];
    float* out = (float*)d_out;

    float *xp, *h1p, *h2p;
    cudaGetSymbolAddress((void**)&xp,  g_x);
    cudaGetSymbolAddress((void**)&h1p, g_h1);
    cudaGetSymbolAddress((void**)&h2p, g_h2);

    // 1) embeddings + FM (writes g_x[:, 0:320] and g_fm)
    embed_fm_kernel<<<BATCH / 4, 256>>>(uid, hour, scale, gender, age, attribute,
                                        user_emb, hour_emb, gender_emb, age_emb,
                                        attr_emb, fm_w, fm_b);

    // 2) vis = visual @ visu_w^T + visu_b  -> g_x[:, 320:384]
    gemm_kernel<<<dim3(FK / 64, BATCH / 64), 256>>>(
        visual, VISD, visu_w, visu_b, xp, 384, 320, VISD, 0);

    // 3) h1 = relu(x @ w1^T + b1)
    gemm_kernel<<<dim3(HID / 64, BATCH / 64), 256>>>(
        xp, 384, w1, b1, h1p, HID, 0, 384, 1);

    // 4) h2 = relu(h1 @ w2^T + b2)
    gemm_kernel<<<dim3(HID / 64, BATCH / 64), 256>>>(
        h1p, HID, w2, b2, h2p, HID, 0, HID, 1);

    // 5) logits + softmax
    final_kernel<<<BATCH / 8, 256>>>(w3, b3, out);
}

// round 3
// speedup vs baseline: 3.0113x; 3.0113x over previous
#include <cuda_runtime.h>
#include <cstdint>
#include <math.h>

#define BATCH   16384
#define FK      64
#define VISD    2048
#define HID     512
#define NUSERS  1000000
#define VOCAB   (NUSERS + 24 + 2 + 8 + 40)

// Scratch (allocation-free rule: __device__ globals)
__device__ float g_x [BATCH * 384];
__device__ float g_fm[BATCH * 2];
__device__ float g_h1[BATCH * HID];
__device__ float g_h2[BATCH * HID];

// ---------------------------------------------------------------------------
// helpers (portable PTX only — the harness targets compute_103, no 'a' feats)
// ---------------------------------------------------------------------------
__device__ __forceinline__ uint32_t smem_u32(const void* p) {
    uint32_t a;
    asm("{ .reg .u64 t; cvta.to.shared.u64 t, %1; cvt.u32.u64 %0, t; }"
        : "=r"(a) : "l"(p));
    return a;
}
__device__ __forceinline__ void cp16(uint32_t s, const void* g) {
    asm volatile("cp.async.cg.shared.global [%0], [%1], 16;" :: "r"(s), "l"(g));
}
__device__ __forceinline__ void cp_commit() {
    asm volatile("cp.async.commit_group;" ::: "memory");
}
template<int N> __device__ __forceinline__ void cp_wait() {
    asm volatile("cp.async.wait_group %0;" :: "n"(N) : "memory");
}
__device__ __forceinline__ uint32_t f2tf(float f) {
    uint32_t r;
    asm("cvt.rna.tf32.f32 %0, %1;" : "=r"(r) : "f"(f));
    return r;
}
__device__ __forceinline__ void mma_tf32(float d[4], const uint32_t a[4],
                                         const uint32_t b[2]) {
    asm volatile(
        "mma.sync.aligned.m16n8k8.row.col.f32.tf32.tf32.f32 "
        "{%0,%1,%2,%3}, {%4,%5,%6,%7}, {%8,%9}, {%0,%1,%2,%3};"
        : "+f"(d[0]), "+f"(d[1]), "+f"(d[2]), "+f"(d[3])
        : "r"(a[0]), "r"(a[1]), "r"(a[2]), "r"(a[3]), "r"(b[0]), "r"(b[1]));
}

// ---------------------------------------------------------------------------
// tf32 tensor-core GEMM:  C[m, ccol0+n] = A[M,K] @ W[N,K]^T + bias (opt relu)
// Double-buffered cp.async; BK=32; 8 warps; warp tile 32m x (BN/WN)n.
// Smem rows padded to LDT=36 floats -> fragment LDS is bank-conflict-free.
// ---------------------------------------------------------------------------
template<int BM, int BN>
__global__ __launch_bounds__(256, 2) void gemm_mma(
    const float* __restrict__ A, int lda,
    const float* __restrict__ W,
    const float* __restrict__ bias,
    float* __restrict__ C, int ldc, int ccol0,
    int K, int relu)
{
    constexpr int BK  = 32;
    constexpr int LDT = 36;                 // floats per smem row (pad 4)
    constexpr int WM  = BM / 32;            // warps along m (4 or 2)
    constexpr int WN  = 8 / WM;             // warps along n (2 or 4)
    constexpr int TN  = BN / WN / 8;        // n8 tiles per warp (4 or 2)
    constexpr int ASZ = BM * LDT;           // floats per stage
    constexpr int WSZ = BN * LDT;

    extern __shared__ float sm[];
    float* sA = sm;                         // [2][ASZ]
    float* sW = sm + 2 * ASZ;               // [2][WSZ]
    __shared__ float sbias[BN];

    const int tid = threadIdx.x;
    const int m0  = blockIdx.y * BM;
    const int n0  = blockIdx.x * BN;
    const int NC  = K / BK;

    if (tid < BN) sbias[tid] = bias[n0 + tid];

    const uint32_t sAu = smem_u32(sA);
    const uint32_t sWu = smem_u32(sW);

    auto load_tiles = [&](int c) {
        const int st = c & 1;
        const int k0 = c * BK;
        #pragma unroll
        for (int j = 0; j < BM / 32; j++) {         // A: BM rows x 8 x 16B
            int i = tid + j * 256;
            int r = i >> 3, sg = i & 7;
            cp16(sAu + (st * ASZ + r * LDT) * 4 + sg * 16,
                 A + (size_t)(m0 + r) * lda + k0 + sg * 4);
        }
        #pragma unroll
        for (int j = 0; j < BN / 32; j++) {         // W: BN rows x 8 x 16B
            int i = tid + j * 256;
            int r = i >> 3, sg = i & 7;
            cp16(sWu + (st * WSZ + r * LDT) * 4 + sg * 16,
                 W + (size_t)(n0 + r) * K + k0 + sg * 4);
        }
    };

    const int lane = tid & 31, warp = tid >> 5;
    const int g = lane >> 2, t = lane & 3;
    const int wm = warp % WM, wn = warp / WM;
    const int mbase = wm * 32;
    const int nbase = wn * (BN / WN);

    float acc[2][TN][4] = {};

    load_tiles(0);
    cp_commit();

    for (int c = 0; c < NC; c++) {
        if (c + 1 < NC) load_tiles(c + 1);
        cp_commit();
        cp_wait<1>();
        __syncthreads();

        const float* pa = sA + (c & 1) * ASZ;
        const float* pw = sW + (c & 1) * WSZ;

        #pragma unroll
        for (int ks = 0; ks < 4; ks++) {
            const int col = ks * 8 + t;
            uint32_t af[2][4], bf[TN][2];
            #pragma unroll
            for (int tm = 0; tm < 2; tm++) {
                const int row = mbase + tm * 16 + g;
                af[tm][0] = f2tf(pa[ row      * LDT + col    ]);
                af[tm][1] = f2tf(pa[(row + 8) * LDT + col    ]);
                af[tm][2] = f2tf(pa[ row      * LDT + col + 4]);
                af[tm][3] = f2tf(pa[(row + 8) * LDT + col + 4]);
            }
            #pragma unroll
            for (int tn = 0; tn < TN; tn++) {
                const int r = nbase + tn * 8 + g;
                bf[tn][0] = f2tf(pw[r * LDT + col    ]);
                bf[tn][1] = f2tf(pw[r * LDT + col + 4]);
            }
            #pragma unroll
            for (int tm = 0; tm < 2; tm++)
                #pragma unroll
                for (int tn = 0; tn < TN; tn++)
                    mma_tf32(acc[tm][tn], af[tm], bf[tn]);
        }
        __syncthreads();
    }

    // epilogue: bias (+relu), float2 stores
    #pragma unroll
    for (int tm = 0; tm < 2; tm++) {
        #pragma unroll
        for (int tn = 0; tn < TN; tn++) {
            const int ncol = nbase + tn * 8 + 2 * t;
            const float b0 = sbias[ncol], b1 = sbias[ncol + 1];
            const int gcol = ccol0 + n0 + ncol;
            #pragma unroll
            for (int half = 0; half < 2; half++) {
                const int row = m0 + mbase + tm * 16 + g + half * 8;
                float2 v;
                v.x = acc[tm][tn][half * 2 + 0] + b0;
                v.y = acc[tm][tn][half * 2 + 1] + b1;
                if (relu) { v.x = fmaxf(v.x, 0.f); v.y = fmaxf(v.y, 0.f); }
                *(float2*)(C + (size_t)row * ldc + gcol) = v;
            }
        }
    }
}

// ---------------------------------------------------------------------------
// Kernel 1: embedding gathers, tanh*scale, FM second order, fm_w gather.
// ---------------------------------------------------------------------------
__global__ void embed_fm_kernel(
    const int* __restrict__ uid, const int* __restrict__ hour,
    const float* __restrict__ scale,
    const int* __restrict__ gender, const int* __restrict__ age,
    const int* __restrict__ attr,
    const float* __restrict__ user_emb, const float* __restrict__ hour_emb,
    const float* __restrict__ gender_emb, const float* __restrict__ age_emb,
    const float* __restrict__ attr_emb,
    const float* __restrict__ fm_w, const float* __restrict__ fm_b)
{
    int s = threadIdx.x >> 6;
    int k = threadIdx.x & 63;
    int b = blockIdx.x * 4 + s;

    int u  = uid[b];
    int h  = hour[b];
    int g  = gender[b];
    int a  = age[b];
    int at = attr[b];
    float sc = scale[b];

    float e0 = user_emb[(long)u * 64 + k];
    float e1 = hour_emb[h * 64 + k];
    float e2 = sc * tanhf(gender_emb[g * 64 + k]);
    float e3 = sc * tanhf(attr_emb[at * 64 + k]);
    float e4 = sc * tanhf(age_emb[a * 64 + k]);

    float* xb = g_x + (long)b * 384;
    xb[      k] = e0;
    xb[ 64 + k] = e1;
    xb[128 + k] = e2;
    xb[192 + k] = e3;
    xb[256 + k] = e4;

    float su = e0 + e1 + e2 + e3 + e4;
    float sq = e0*e0 + e1*e1 + e2*e2 + e3*e3 + e4*e4;
    float so = su * su - sq;

    #pragma unroll
    for (int o = 16; o > 0; o >>= 1)
        so += __shfl_down_sync(0xffffffffu, so, o);

    __shared__ float red[4][2];
    if ((k & 31) == 0) red[s][k >> 5] = so;
    __syncthreads();

    if (k == 0) {
        float second = 0.5f * (red[s][0] + red[s][1]);
        long c0 = u;
        long c1 = NUSERS + h;
        long c2 = NUSERS + 24 + g;
        long c3 = NUSERS + 26 + a;
        long c4 = NUSERS + 34 + at;
        #pragma unroll
        for (int j = 0; j < 2; j++) {
            const float* w = fm_w + (long)j * VOCAB;
            g_fm[b * 2 + j] =
                w[c0] + w[c1] + w[c2] + w[c3] + w[c4] + fm_b[j] + second;
        }
    }
}

// ---------------------------------------------------------------------------
// Kernel 5: logits = fm + h2 @ w3^T + b3 ; softmax over 2 classes.
// ---------------------------------------------------------------------------
__global__ void final_kernel(const float* __restrict__ w3,
                             const float* __restrict__ b3,
                             float* __restrict__ out)
{
    __shared__ float w3s[2 * HID];
    int t = threadIdx.x;
    for (int i = t; i < 2 * HID; i += 256) w3s[i] = w3[i];
    __syncthreads();

    int warp = t >> 5, lane = t & 31;
    int b = blockIdx.x * 8 + warp;
    const float* h = g_h2 + (long)b * HID;

    float d0 = 0.f, d1 = 0.f;
    #pragma unroll
    for (int i = lane; i < HID; i += 32) {
        float hv = h[i];
        d0 = fmaf(hv, w3s[i],       d0);
        d1 = fmaf(hv, w3s[HID + i], d1);
    }
    #pragma unroll
    for (int o = 16; o > 0; o >>= 1) {
        d0 += __shfl_down_sync(0xffffffffu, d0, o);
        d1 += __shfl_down_sync(0xffffffffu, d1, o);
    }
    if (lane == 0) {
        float l0 = g_fm[b * 2 + 0] + b3[0] + d0;
        float l1 = g_fm[b * 2 + 1] + b3[1] + d1;
        float m  = fmaxf(l0, l1);
        float e0 = expf(l0 - m), e1 = expf(l1 - m);
        float inv = 1.0f / (e0 + e1);
        out[b * 2 + 0] = e0 * inv;
        out[b * 2 + 1] = e1 * inv;
    }
}

// ---------------------------------------------------------------------------
extern "C" void kernel_launch(void* const* d_in, const int* in_sizes, int n_in,
                              void* d_out, int out_size)
{
    const int*   uid        = (const int*)  d_in[0];
    const int*   hour       = (const int*)  d_in[1];
    const float* visual     = (const float*)d_in[2];
    const float* scale      = (const float*)d_in[3];
    const int*   gender     = (const int*)  d_in[4];
    const int*   age        = (const int*)  d_in[5];
    const int*   attribute  = (const int*)  d_in[6];
    const float* user_emb   = (const float*)d_in[7];
    const float* hour_emb   = (const float*)d_in[8];
    const float* gender_emb = (const float*)d_in[9];
    const float* age_emb    = (const float*)d_in[10];
    const float* attr_emb   = (const float*)d_in[11];
    const float* visu_w     = (const float*)d_in[12];
    const float* visu_b     = (const float*)d_in[13];
    const float* fm_w       = (const float*)d_in[14];
    const float* fm_b       = (const float*)d_in[15];
    const float* w1         = (const float*)d_in[16];
    const float* b1         = (const float*)d_in[17];
    const float* w2         = (const float*)d_in[18];
    const float* b2         = (const float*)d_in[19];
    const float* w3         = (const float*)d_in[20];
    const float* b3         = (const float*)d_in[21];
    float* out = (float*)d_out;

    float *xp, *h1p, *h2p;
    cudaGetSymbolAddress((void**)&xp,  g_x);
    cudaGetSymbolAddress((void**)&h1p, g_h1);
    cudaGetSymbolAddress((void**)&h2p, g_h2);

    // dynamic smem (2 stages): 2*(BM+BN)*36 floats
    const int SM_64_64  = 2 * (64  + 64) * 36 * 4;   // 36,864 B
    const int SM_128_64 = 2 * (128 + 64) * 36 * 4;   // 55,296 B
    cudaFuncSetAttribute(gemm_mma<64, 64>,  cudaFuncAttributeMaxDynamicSharedMemorySize, SM_64_64);
    cudaFuncSetAttribute(gemm_mma<128, 64>, cudaFuncAttributeMaxDynamicSharedMemorySize, SM_128_64);

    // 1) embeddings + FM (writes g_x[:, 0:320] and g_fm)
    embed_fm_kernel<<<BATCH / 4, 256>>>(uid, hour, scale, gender, age, attribute,
                                        user_emb, hour_emb, gender_emb, age_emb,
                                        attr_emb, fm_w, fm_b);

    // 2) vis = visual @ visu_w^T + visu_b  -> g_x[:, 320:384]   (256 CTAs)
    gemm_mma<64, 64><<<dim3(1, BATCH / 64), 256, SM_64_64>>>(
        visual, VISD, visu_w, visu_b, xp, 384, 320, VISD, 0);

    // 3) h1 = relu(x @ w1^T + b1)
    gemm_mma<128, 64><<<dim3(HID / 64, BATCH / 128), 256, SM_128_64>>>(
        xp, 384, w1, b1, h1p, HID, 0, 384, 1);

    // 4) h2 = relu(h1 @ w2^T + b2)
    gemm_mma<128, 64><<<dim3(HID / 64, BATCH / 128), 256, SM_128_64>>>(
        h1p, HID, w2, b2, h2p, HID, 0, HID, 1);

    // 5) logits + softmax
    final_kernel<<<BATCH / 8, 256>>>(w3, b3, out);
}

// round 4
// speedup vs baseline: 3.3765x; 1.1213x over previous
#include <cuda_runtime.h>
#include <cstdint>
#include <math.h>

#define BATCH   16384
#define FK      64
#define VISD    2048
#define HID     512
#define NUSERS  1000000
#define VOCAB   (NUSERS + 24 + 2 + 8 + 40)

// Scratch (allocation-free rule: __device__ globals)
__device__ float g_x [BATCH * 384];
__device__ float g_fm[BATCH * 2];
__device__ float g_h1[BATCH * HID];
__device__ float g_h2[BATCH * HID];

// ---------------------------------------------------------------------------
// helpers (portable PTX only — harness targets compute_103, no 'a' features)
// ---------------------------------------------------------------------------
__device__ __forceinline__ uint32_t smem_u32(const void* p) {
    uint32_t a;
    asm("{ .reg .u64 t; cvta.to.shared.u64 t, %1; cvt.u32.u64 %0, t; }"
        : "=r"(a) : "l"(p));
    return a;
}
__device__ __forceinline__ void cp16(uint32_t s, const void* g) {
    asm volatile("cp.async.cg.shared.global [%0], [%1], 16;" :: "r"(s), "l"(g));
}
__device__ __forceinline__ void cp_commit() {
    asm volatile("cp.async.commit_group;" ::: "memory");
}
template<int N> __device__ __forceinline__ void cp_wait() {
    asm volatile("cp.async.wait_group %0;" :: "n"(N) : "memory");
}
// Raw fp32 bits fed to tf32 MMA == RZ-truncated tf32 (hardware reads top 19 bits).
__device__ __forceinline__ void mma_tf32(float d[4], const uint32_t a[4],
                                         const uint32_t b[2]) {
    asm volatile(
        "mma.sync.aligned.m16n8k8.row.col.f32.tf32.tf32.f32 "
        "{%0,%1,%2,%3}, {%4,%5,%6,%7}, {%8,%9}, {%0,%1,%2,%3};"
        : "+f"(d[0]), "+f"(d[1]), "+f"(d[2]), "+f"(d[3])
        : "r"(a[0]), "r"(a[1]), "r"(a[2]), "r"(a[3]), "r"(b[0]), "r"(b[1]));
}

// ---------------------------------------------------------------------------
// tf32 tensor-core GEMM:  C[m, ccol0+n] = A[M,K] @ W[N,K]^T + bias (opt relu)
// Double-buffered cp.async; BK=32; 8 warps.
//   <128,128>: warps 4x2, warp tile 32x64 (TN=8)  -> 1.5 LDS/MMA
//   <64,64>  : warps 2x4, warp tile 32x16 (TN=2)
// Smem rows padded to LDT=36 floats -> conflict-free fragment LDS.
// ---------------------------------------------------------------------------
template<int BM, int BN>
__global__ __launch_bounds__(256, 2) void gemm_mma(
    const float* __restrict__ A, int lda,
    const float* __restrict__ W,
    const float* __restrict__ bias,
    float* __restrict__ C, int ldc, int ccol0,
    int K, int relu)
{
    constexpr int BK  = 32;
    constexpr int LDT = 36;
    constexpr int WM  = BM / 32;            // warps along m
    constexpr int WN  = 8 / WM;             // warps along n
    constexpr int TN  = BN / WN / 8;        // n8 tiles per warp
    constexpr int ASZ = BM * LDT;
    constexpr int WSZ = BN * LDT;

    extern __shared__ float sm[];
    float* sA = sm;                         // [2][ASZ]
    float* sW = sm + 2 * ASZ;               // [2][WSZ]
    __shared__ float sbias[BN];

    const int tid = threadIdx.x;
    const int m0  = blockIdx.y * BM;
    const int n0  = blockIdx.x * BN;
    const int NC  = K / BK;

    if (tid < BN) sbias[tid] = bias[n0 + tid];

    const uint32_t sAu = smem_u32(sA);
    const uint32_t sWu = smem_u32(sW);

    auto load_tiles = [&](int c) {
        const int st = c & 1;
        const int k0 = c * BK;
        #pragma unroll
        for (int j = 0; j < BM / 32; j++) {
            int i = tid + j * 256;
            int r = i >> 3, sg = i & 7;
            cp16(sAu + (st * ASZ + r * LDT) * 4 + sg * 16,
                 A + (size_t)(m0 + r) * lda + k0 + sg * 4);
        }
        #pragma unroll
        for (int j = 0; j < BN / 32; j++) {
            int i = tid + j * 256;
            int r = i >> 3, sg = i & 7;
            cp16(sWu + (st * WSZ + r * LDT) * 4 + sg * 16,
                 W + (size_t)(n0 + r) * K + k0 + sg * 4);
        }
    };

    const int lane = tid & 31, warp = tid >> 5;
    const int g = lane >> 2, t = lane & 3;
    const int wm = warp % WM, wn = warp / WM;
    const int mbase = wm * 32;
    const int nbase = wn * (BN / WN);

    float acc[2][TN][4] = {};

    load_tiles(0);
    cp_commit();

    for (int c = 0; c < NC; c++) {
        if (c + 1 < NC) load_tiles(c + 1);
        cp_commit();
        cp_wait<1>();
        __syncthreads();

        const uint32_t* pa = (const uint32_t*)(sA + (c & 1) * ASZ);
        const uint32_t* pw = (const uint32_t*)(sW + (c & 1) * WSZ);

        #pragma unroll
        for (int ks = 0; ks < 4; ks++) {
            const int col = ks * 8 + t;
            uint32_t af[2][4], bf[TN][2];
            #pragma unroll
            for (int tm = 0; tm < 2; tm++) {
                const int row = mbase + tm * 16 + g;
                af[tm][0] = pa[ row      * LDT + col    ];
                af[tm][1] = pa[(row + 8) * LDT + col    ];
                af[tm][2] = pa[ row      * LDT + col + 4];
                af[tm][3] = pa[(row + 8) * LDT + col + 4];
            }
            #pragma unroll
            for (int tn = 0; tn < TN; tn++) {
                const int r = nbase + tn * 8 + g;
                bf[tn][0] = pw[r * LDT + col    ];
                bf[tn][1] = pw[r * LDT + col + 4];
            }
            #pragma unroll
            for (int tm = 0; tm < 2; tm++)
                #pragma unroll
                for (int tn = 0; tn < TN; tn++)
                    mma_tf32(acc[tm][tn], af[tm], bf[tn]);
        }
        __syncthreads();
    }

    // epilogue: bias (+relu), float2 stores
    #pragma unroll
    for (int tm = 0; tm < 2; tm++) {
        #pragma unroll
        for (int tn = 0; tn < TN; tn++) {
            const int ncol = nbase + tn * 8 + 2 * t;
            const float b0 = sbias[ncol], b1 = sbias[ncol + 1];
            const int gcol = ccol0 + n0 + ncol;
            #pragma unroll
            for (int half = 0; half < 2; half++) {
                const int row = m0 + mbase + tm * 16 + g + half * 8;
                float2 v;
                v.x = acc[tm][tn][half * 2 + 0] + b0;
                v.y = acc[tm][tn][half * 2 + 1] + b1;
                if (relu) { v.x = fmaxf(v.x, 0.f); v.y = fmaxf(v.y, 0.f); }
                *(float2*)(C + (size_t)row * ldc + gcol) = v;
            }
        }
    }
}

// ---------------------------------------------------------------------------
// Kernel 1: embedding gathers, tanh*scale, FM second order, fm_w gather.
// ---------------------------------------------------------------------------
__global__ void embed_fm_kernel(
    const int* __restrict__ uid, const int* __restrict__ hour,
    const float* __restrict__ scale,
    const int* __restrict__ gender, const int* __restrict__ age,
    const int* __restrict__ attr,
    const float* __restrict__ user_emb, const float* __restrict__ hour_emb,
    const float* __restrict__ gender_emb, const float* __restrict__ age_emb,
    const float* __restrict__ attr_emb,
    const float* __restrict__ fm_w, const float* __restrict__ fm_b)
{
    int s = threadIdx.x >> 6;
    int k = threadIdx.x & 63;
    int b = blockIdx.x * 4 + s;

    int u  = uid[b];
    int h  = hour[b];
    int g  = gender[b];
    int a  = age[b];
    int at = attr[b];
    float sc = scale[b];

    float e0 = user_emb[(long)u * 64 + k];
    float e1 = hour_emb[h * 64 + k];
    float e2 = sc * tanhf(gender_emb[g * 64 + k]);
    float e3 = sc * tanhf(attr_emb[at * 64 + k]);
    float e4 = sc * tanhf(age_emb[a * 64 + k]);

    float* xb = g_x + (long)b * 384;
    xb[      k] = e0;
    xb[ 64 + k] = e1;
    xb[128 + k] = e2;
    xb[192 + k] = e3;
    xb[256 + k] = e4;

    float su = e0 + e1 + e2 + e3 + e4;
    float sq = e0*e0 + e1*e1 + e2*e2 + e3*e3 + e4*e4;
    float so = su * su - sq;

    #pragma unroll
    for (int o = 16; o > 0; o >>= 1)
        so += __shfl_down_sync(0xffffffffu, so, o);

    __shared__ float red[4][2];
    if ((k & 31) == 0) red[s][k >> 5] = so;
    __syncthreads();

    if (k == 0) {
        float second = 0.5f * (red[s][0] + red[s][1]);
        long c0 = u;
        long c1 = NUSERS + h;
        long c2 = NUSERS + 24 + g;
        long c3 = NUSERS + 26 + a;
        long c4 = NUSERS + 34 + at;
        #pragma unroll
        for (int j = 0; j < 2; j++) {
            const float* w = fm_w + (long)j * VOCAB;
            g_fm[b * 2 + j] =
                w[c0] + w[c1] + w[c2] + w[c3] + w[c4] + fm_b[j] + second;
        }
    }
}

// ---------------------------------------------------------------------------
// Kernel 5: logits = fm + h2 @ w3^T + b3 ; softmax over 2 classes.
// ---------------------------------------------------------------------------
__global__ void final_kernel(const float* __restrict__ w3,
                             const float* __restrict__ b3,
                             float* __restrict__ out)
{
    __shared__ float w3s[2 * HID];
    int t = threadIdx.x;
    for (int i = t; i < 2 * HID; i += 256) w3s[i] = w3[i];
    __syncthreads();

    int warp = t >> 5, lane = t & 31;
    int b = blockIdx.x * 8 + warp;
    const float* h = g_h2 + (long)b * HID;

    float d0 = 0.f, d1 = 0.f;
    #pragma unroll
    for (int i = lane; i < HID; i += 32) {
        float hv = h[i];
        d0 = fmaf(hv, w3s[i],       d0);
        d1 = fmaf(hv, w3s[HID + i], d1);
    }
    #pragma unroll
    for (int o = 16; o > 0; o >>= 1) {
        d0 += __shfl_down_sync(0xffffffffu, d0, o);
        d1 += __shfl_down_sync(0xffffffffu, d1, o);
    }
    if (lane == 0) {
        float l0 = g_fm[b * 2 + 0] + b3[0] + d0;
        float l1 = g_fm[b * 2 + 1] + b3[1] + d1;
        float m  = fmaxf(l0, l1);
        float e0 = expf(l0 - m), e1 = expf(l1 - m);
        float inv = 1.0f / (e0 + e1);
        out[b * 2 + 0] = e0 * inv;
        out[b * 2 + 1] = e1 * inv;
    }
}

// ---------------------------------------------------------------------------
extern "C" void kernel_launch(void* const* d_in, const int* in_sizes, int n_in,
                              void* d_out, int out_size)
{
    const int*   uid        = (const int*)  d_in[0];
    const int*   hour       = (const int*)  d_in[1];
    const float* visual     = (const float*)d_in[2];
    const float* scale      = (const float*)d_in[3];
    const int*   gender     = (const int*)  d_in[4];
    const int*   age        = (const int*)  d_in[5];
    const int*   attribute  = (const int*)  d_in[6];
    const float* user_emb   = (const float*)d_in[7];
    const float* hour_emb   = (const float*)d_in[8];
    const float* gender_emb = (const float*)d_in[9];
    const float* age_emb    = (const float*)d_in[10];
    const float* attr_emb   = (const float*)d_in[11];
    const float* visu_w     = (const float*)d_in[12];
    const float* visu_b     = (const float*)d_in[13];
    const float* fm_w       = (const float*)d_in[14];
    const float* fm_b       = (const float*)d_in[15];
    const float* w1         = (const float*)d_in[16];
    const float* b1         = (const float*)d_in[17];
    const float* w2         = (const float*)d_in[18];
    const float* b2         = (const float*)d_in[19];
    const float* w3         = (const float*)d_in[20];
    const float* b3         = (const float*)d_in[21];
    float* out = (float*)d_out;

    float *xp, *h1p, *h2p;
    cudaGetSymbolAddress((void**)&xp,  g_x);
    cudaGetSymbolAddress((void**)&h1p, g_h1);
    cudaGetSymbolAddress((void**)&h2p, g_h2);

    const int SM_64_64   = 2 * (64  + 64)  * 36 * 4;   // 36,864 B
    const int SM_128_128 = 2 * (128 + 128) * 36 * 4;   // 73,728 B
    cudaFuncSetAttribute(gemm_mma<64, 64>,   cudaFuncAttributeMaxDynamicSharedMemorySize, SM_64_64);
    cudaFuncSetAttribute(gemm_mma<128, 128>, cudaFuncAttributeMaxDynamicSharedMemorySize, SM_128_128);

    // 1) embeddings + FM (writes g_x[:, 0:320] and g_fm)
    embed_fm_kernel<<<BATCH / 4, 256>>>(uid, hour, scale, gender, age, attribute,
                                        user_emb, hour_emb, gender_emb, age_emb,
                                        attr_emb, fm_w, fm_b);

    // 2) vis = visual @ visu_w^T + visu_b  -> g_x[:, 320:384]   (256 CTAs)
    gemm_mma<64, 64><<<dim3(1, BATCH / 64), 256, SM_64_64>>>(
        visual, VISD, visu_w, visu_b, xp, 384, 320, VISD, 0);

    // 3) h1 = relu(x @ w1^T + b1)   (512 CTAs)
    gemm_mma<128, 128><<<dim3(HID / 128, BATCH / 128), 256, SM_128_128>>>(
        xp, 384, w1, b1, h1p, HID, 0, 384, 1);

    // 4) h2 = relu(h1 @ w2^T + b2)  (512 CTAs)
    gemm_mma<128, 128><<<dim3(HID / 128, BATCH / 128), 256, SM_128_128>>>(
        h1p, HID, w2, b2, h2p, HID, 0, HID, 1);

    // 5) logits + softmax
    final_kernel<<<BATCH / 8, 256>>>(w3, b3, out);
}

// round 5
// speedup vs baseline: 4.3174x; 1.2787x over previous
#include <cuda_runtime.h>
#include <cuda_bf16.h>
#include <cstdint>
#include <math.h>

#define BATCH   16384
#define FK      64
#define VISD    2048
#define HID     512
#define NUSERS  1000000
#define VOCAB   (NUSERS + 24 + 2 + 8 + 40)

// Scratch (allocation-free rule: __device__ globals)
__device__ __nv_bfloat16 g_xh [BATCH * 384];   // DNN input, bf16
__device__ __nv_bfloat16 g_h1h[BATCH * HID];   // hidden1, bf16
__device__ __nv_bfloat16 g_h2h[BATCH * HID];   // hidden2, bf16
__device__ __nv_bfloat16 g_w1h[HID * 384];     // w1 converted
__device__ __nv_bfloat16 g_w2h[HID * HID];     // w2 converted
__device__ float         g_fm [BATCH * 2];

// ---------------------------------------------------------------------------
// helpers (portable PTX only — harness targets compute_103, no 'a' features)
// ---------------------------------------------------------------------------
__device__ __forceinline__ uint32_t smem_u32(const void* p) {
    uint32_t a;
    asm("{ .reg .u64 t; cvta.to.shared.u64 t, %1; cvt.u32.u64 %0, t; }"
        : "=r"(a) : "l"(p));
    return a;
}
__device__ __forceinline__ void cp16(uint32_t s, const void* g) {
    asm volatile("cp.async.cg.shared.global [%0], [%1], 16;" :: "r"(s), "l"(g));
}
__device__ __forceinline__ void cp_commit() {
    asm volatile("cp.async.commit_group;" ::: "memory");
}
template<int N> __device__ __forceinline__ void cp_wait() {
    asm volatile("cp.async.wait_group %0;" :: "n"(N) : "memory");
}
// Raw fp32 bits fed to tf32 MMA == RZ-truncated tf32.
__device__ __forceinline__ void mma_tf32(float d[4], const uint32_t a[4],
                                         const uint32_t b[2]) {
    asm volatile(
        "mma.sync.aligned.m16n8k8.row.col.f32.tf32.tf32.f32 "
        "{%0,%1,%2,%3}, {%4,%5,%6,%7}, {%8,%9}, {%0,%1,%2,%3};"
        : "+f"(d[0]), "+f"(d[1]), "+f"(d[2]), "+f"(d[3])
        : "r"(a[0]), "r"(a[1]), "r"(a[2]), "r"(a[3]), "r"(b[0]), "r"(b[1]));
}
__device__ __forceinline__ void mma_bf16(float d[4], const uint32_t a[4],
                                         const uint32_t b[2]) {
    asm volatile(
        "mma.sync.aligned.m16n8k16.row.col.f32.bf16.bf16.f32 "
        "{%0,%1,%2,%3}, {%4,%5,%6,%7}, {%8,%9}, {%0,%1,%2,%3};"
        : "+f"(d[0]), "+f"(d[1]), "+f"(d[2]), "+f"(d[3])
        : "r"(a[0]), "r"(a[1]), "r"(a[2]), "r"(a[3]), "r"(b[0]), "r"(b[1]));
}
__device__ __forceinline__ uint32_t pack_bf16(float lo, float hi) {
    uint32_t r;
    asm("cvt.rn.bf16x2.f32 %0, %1, %2;" : "=r"(r) : "f"(hi), "f"(lo));
    return r;
}

// ---------------------------------------------------------------------------
// Weight conversion: w1, w2 fp32 -> bf16 (once per launch, ~458K floats)
// ---------------------------------------------------------------------------
__global__ void conv_w_kernel(const float* __restrict__ w1,
                              const float* __restrict__ w2)
{
    const int N1 = HID * 384 / 4;           // float4 count in w1
    int i = blockIdx.x * blockDim.x + threadIdx.x;
    if (i < N1) {
        float4 v = ((const float4*)w1)[i];
        uint2 o = { pack_bf16(v.x, v.y), pack_bf16(v.z, v.w) };
        ((uint2*)g_w1h)[i] = o;
    } else {
        int j = i - N1;
        float4 v = ((const float4*)w2)[j];
        uint2 o = { pack_bf16(v.x, v.y), pack_bf16(v.z, v.w) };
        ((uint2*)g_w2h)[j] = o;
    }
}

// ---------------------------------------------------------------------------
// tf32 tensor-core GEMM (vis layer): C = A[M,K] @ W[N,K]^T + bias
// Double-buffered cp.async; BK=32; 8 warps. Output written as bf16.
// ---------------------------------------------------------------------------
template<int BM, int BN>
__global__ __launch_bounds__(256, 2) void gemm_tf32(
    const float* __restrict__ A, int lda,
    const float* __restrict__ W,
    const float* __restrict__ bias,
    __nv_bfloat16* __restrict__ C, int ldc, int ccol0,
    int K)
{
    constexpr int BK  = 32;
    constexpr int LDT = 36;
    constexpr int WM  = BM / 32;
    constexpr int WN  = 8 / WM;
    constexpr int TN  = BN / WN / 8;
    constexpr int ASZ = BM * LDT;
    constexpr int WSZ = BN * LDT;

    extern __shared__ float sm[];
    float* sA = sm;
    float* sW = sm + 2 * ASZ;
    __shared__ float sbias[BN];

    const int tid = threadIdx.x;
    const int m0  = blockIdx.y * BM;
    const int n0  = blockIdx.x * BN;
    const int NC  = K / BK;

    if (tid < BN) sbias[tid] = bias[n0 + tid];

    const uint32_t sAu = smem_u32(sA);
    const uint32_t sWu = smem_u32(sW);

    auto load_tiles = [&](int c) {
        const int st = c & 1;
        const int k0 = c * BK;
        #pragma unroll
        for (int j = 0; j < BM / 32; j++) {
            int i = tid + j * 256;
            int r = i >> 3, sg = i & 7;
            cp16(sAu + (st * ASZ + r * LDT) * 4 + sg * 16,
                 A + (size_t)(m0 + r) * lda + k0 + sg * 4);
        }
        #pragma unroll
        for (int j = 0; j < BN / 32; j++) {
            int i = tid + j * 256;
            int r = i >> 3, sg = i & 7;
            cp16(sWu + (st * WSZ + r * LDT) * 4 + sg * 16,
                 W + (size_t)(n0 + r) * K + k0 + sg * 4);
        }
    };

    const int lane = tid & 31, warp = tid >> 5;
    const int g = lane >> 2, t = lane & 3;
    const int wm = warp % WM, wn = warp / WM;
    const int mbase = wm * 32;
    const int nbase = wn * (BN / WN);

    float acc[2][TN][4] = {};

    load_tiles(0);
    cp_commit();

    for (int c = 0; c < NC; c++) {
        if (c + 1 < NC) load_tiles(c + 1);
        cp_commit();
        cp_wait<1>();
        __syncthreads();

        const uint32_t* pa = (const uint32_t*)(sA + (c & 1) * ASZ);
        const uint32_t* pw = (const uint32_t*)(sW + (c & 1) * WSZ);

        #pragma unroll
        for (int ks = 0; ks < 4; ks++) {
            const int col = ks * 8 + t;
            uint32_t af[2][4], bf[TN][2];
            #pragma unroll
            for (int tm = 0; tm < 2; tm++) {
                const int row = mbase + tm * 16 + g;
                af[tm][0] = pa[ row      * LDT + col    ];
                af[tm][1] = pa[(row + 8) * LDT + col    ];
                af[tm][2] = pa[ row      * LDT + col + 4];
                af[tm][3] = pa[(row + 8) * LDT + col + 4];
            }
            #pragma unroll
            for (int tn = 0; tn < TN; tn++) {
                const int r = nbase + tn * 8 + g;
                bf[tn][0] = pw[r * LDT + col    ];
                bf[tn][1] = pw[r * LDT + col + 4];
            }
            #pragma unroll
            for (int tm = 0; tm < 2; tm++)
                #pragma unroll
                for (int tn = 0; tn < TN; tn++)
                    mma_tf32(acc[tm][tn], af[tm], bf[tn]);
        }
        __syncthreads();
    }

    // epilogue: bias, pack bf16x2 stores
    #pragma unroll
    for (int tm = 0; tm < 2; tm++) {
        #pragma unroll
        for (int tn = 0; tn < TN; tn++) {
            const int ncol = nbase + tn * 8 + 2 * t;
            const float b0 = sbias[ncol], b1 = sbias[ncol + 1];
            const int gcol = ccol0 + n0 + ncol;
            #pragma unroll
            for (int half = 0; half < 2; half++) {
                const int row = m0 + mbase + tm * 16 + g + half * 8;
                float vx = acc[tm][tn][half * 2 + 0] + b0;
                float vy = acc[tm][tn][half * 2 + 1] + b1;
                *(uint32_t*)(C + (size_t)row * ldc + gcol) = pack_bf16(vx, vy);
            }
        }
    }
}

// ---------------------------------------------------------------------------
// bf16 tensor-core GEMM (MLP layers): C = A[M,K] @ W[N,K]^T + bias, relu
// m16n8k16; BK=32 elements (16 words); row pad to 20 words (conflict-free).
// ---------------------------------------------------------------------------
template<int BM, int BN>
__global__ __launch_bounds__(256, 2) void gemm_bf16k(
    const __nv_bfloat16* __restrict__ A, int lda,
    const __nv_bfloat16* __restrict__ W,
    const float* __restrict__ bias,
    __nv_bfloat16* __restrict__ C, int ldc,
    int K, int relu)
{
    constexpr int BK  = 32;                 // bf16 elements per chunk
    constexpr int LDW = 20;                 // u32 words per smem row (16+4 pad)
    constexpr int WM  = BM / 32;
    constexpr int WN  = 8 / WM;
    constexpr int TN  = BN / WN / 8;
    constexpr int ASZ = BM * LDW;           // words per stage
    constexpr int WSZ = BN * LDW;

    extern __shared__ uint32_t smw[];
    uint32_t* sA = smw;
    uint32_t* sW = smw + 2 * ASZ;
    __shared__ float sbias[BN];

    const int tid = threadIdx.x;
    const int m0  = blockIdx.y * BM;
    const int n0  = blockIdx.x * BN;
    const int NC  = K / BK;

    if (tid < BN) sbias[tid] = bias[n0 + tid];

    const uint32_t sAu = smem_u32(sA);
    const uint32_t sWu = smem_u32(sW);

    auto load_tiles = [&](int c) {
        const int st = c & 1;
        const int k0 = c * BK;
        #pragma unroll
        for (int j = 0; j < BM / 64; j++) {          // BM rows x 4 x 16B
            int i = tid + j * 256;
            int r = i >> 2, sg = i & 3;
            cp16(sAu + (st * ASZ + r * LDW + sg * 4) * 4,
                 A + (size_t)(m0 + r) * lda + k0 + sg * 8);
        }
        #pragma unroll
        for (int j = 0; j < BN / 64; j++) {
            int i = tid + j * 256;
            int r = i >> 2, sg = i & 3;
            cp16(sWu + (st * WSZ + r * LDW + sg * 4) * 4,
                 W + (size_t)(n0 + r) * K + k0 + sg * 8);
        }
    };

    const int lane = tid & 31, warp = tid >> 5;
    const int g = lane >> 2, t = lane & 3;
    const int wm = warp % WM, wn = warp / WM;
    const int mbase = wm * 32;
    const int nbase = wn * (BN / WN);

    float acc[2][TN][4] = {};

    load_tiles(0);
    cp_commit();

    for (int c = 0; c < NC; c++) {
        if (c + 1 < NC) load_tiles(c + 1);
        cp_commit();
        cp_wait<1>();
        __syncthreads();

        const uint32_t* pa = sA + (c & 1) * ASZ;
        const uint32_t* pw = sW + (c & 1) * WSZ;

        #pragma unroll
        for (int ks = 0; ks < 2; ks++) {            // two k16 steps per chunk
            const int col = ks * 8 + t;
            uint32_t af[2][4], bf[TN][2];
            #pragma unroll
            for (int tm = 0; tm < 2; tm++) {
                const int row = mbase + tm * 16 + g;
                af[tm][0] = pa[ row      * LDW + col    ];
                af[tm][1] = pa[(row + 8) * LDW + col    ];
                af[tm][2] = pa[ row      * LDW + col + 4];
                af[tm][3] = pa[(row + 8) * LDW + col + 4];
            }
            #pragma unroll
            for (int tn = 0; tn < TN; tn++) {
                const int r = nbase + tn * 8 + g;
                bf[tn][0] = pw[r * LDW + col    ];
                bf[tn][1] = pw[r * LDW + col + 4];
            }
            #pragma unroll
            for (int tm = 0; tm < 2; tm++)
                #pragma unroll
                for (int tn = 0; tn < TN; tn++)
                    mma_bf16(acc[tm][tn], af[tm], bf[tn]);
        }
        __syncthreads();
    }

    // epilogue: bias (+relu), pack bf16x2 stores
    #pragma unroll
    for (int tm = 0; tm < 2; tm++) {
        #pragma unroll
        for (int tn = 0; tn < TN; tn++) {
            const int ncol = nbase + tn * 8 + 2 * t;
            const float b0 = sbias[ncol], b1 = sbias[ncol + 1];
            const int gcol = n0 + ncol;
            #pragma unroll
            for (int half = 0; half < 2; half++) {
                const int row = m0 + mbase + tm * 16 + g + half * 8;
                float vx = acc[tm][tn][half * 2 + 0] + b0;
                float vy = acc[tm][tn][half * 2 + 1] + b1;
                if (relu) { vx = fmaxf(vx, 0.f); vy = fmaxf(vy, 0.f); }
                *(uint32_t*)(C + (size_t)row * ldc + gcol) = pack_bf16(vx, vy);
            }
        }
    }
}

// ---------------------------------------------------------------------------
// Kernel 1: embedding gathers, tanh*scale, FM second order, fm_w gather.
// Writes bf16 activations into g_xh[:, 0:320].
// ---------------------------------------------------------------------------
__global__ void embed_fm_kernel(
    const int* __restrict__ uid, const int* __restrict__ hour,
    const float* __restrict__ scale,
    const int* __restrict__ gender, const int* __restrict__ age,
    const int* __restrict__ attr,
    const float* __restrict__ user_emb, const float* __restrict__ hour_emb,
    const float* __restrict__ gender_emb, const float* __restrict__ age_emb,
    const float* __restrict__ attr_emb,
    const float* __restrict__ fm_w, const float* __restrict__ fm_b)
{
    int s = threadIdx.x >> 6;
    int k = threadIdx.x & 63;
    int b = blockIdx.x * 4 + s;

    int u  = uid[b];
    int h  = hour[b];
    int g  = gender[b];
    int a  = age[b];
    int at = attr[b];
    float sc = scale[b];

    float e0 = user_emb[(long)u * 64 + k];
    float e1 = hour_emb[h * 64 + k];
    float e2 = sc * tanhf(gender_emb[g * 64 + k]);
    float e3 = sc * tanhf(attr_emb[at * 64 + k]);
    float e4 = sc * tanhf(age_emb[a * 64 + k]);

    __nv_bfloat16* xb = g_xh + (size_t)b * 384;
    xb[      k] = __float2bfloat16_rn(e0);
    xb[ 64 + k] = __float2bfloat16_rn(e1);
    xb[128 + k] = __float2bfloat16_rn(e2);
    xb[192 + k] = __float2bfloat16_rn(e3);
    xb[256 + k] = __float2bfloat16_rn(e4);

    float su = e0 + e1 + e2 + e3 + e4;
    float sq = e0*e0 + e1*e1 + e2*e2 + e3*e3 + e4*e4;
    float so = su * su - sq;

    #pragma unroll
    for (int o = 16; o > 0; o >>= 1)
        so += __shfl_down_sync(0xffffffffu, so, o);

    __shared__ float red[4][2];
    if ((k & 31) == 0) red[s][k >> 5] = so;
    __syncthreads();

    if (k == 0) {
        float second = 0.5f * (red[s][0] + red[s][1]);
        long c0 = u;
        long c1 = NUSERS + h;
        long c2 = NUSERS + 24 + g;
        long c3 = NUSERS + 26 + a;
        long c4 = NUSERS + 34 + at;
        #pragma unroll
        for (int j = 0; j < 2; j++) {
            const float* w = fm_w + (long)j * VOCAB;
            g_fm[b * 2 + j] =
                w[c0] + w[c1] + w[c2] + w[c3] + w[c4] + fm_b[j] + second;
        }
    }
}

// ---------------------------------------------------------------------------
// Kernel 5: logits = fm + h2 @ w3^T + b3 ; softmax over 2 classes.
// ---------------------------------------------------------------------------
__global__ void final_kernel(const float* __restrict__ w3,
                             const float* __restrict__ b3,
                             float* __restrict__ out)
{
    __shared__ float w3s[2 * HID];
    int t = threadIdx.x;
    for (int i = t; i < 2 * HID; i += 256) w3s[i] = w3[i];
    __syncthreads();

    int warp = t >> 5, lane = t & 31;
    int b = blockIdx.x * 8 + warp;
    const __nv_bfloat16* h = g_h2h + (size_t)b * HID;

    float d0 = 0.f, d1 = 0.f;
    #pragma unroll
    for (int i = lane; i < HID; i += 32) {
        float hv = __bfloat162float(h[i]);
        d0 = fmaf(hv, w3s[i],       d0);
        d1 = fmaf(hv, w3s[HID + i], d1);
    }
    #pragma unroll
    for (int o = 16; o > 0; o >>= 1) {
        d0 += __shfl_down_sync(0xffffffffu, d0, o);
        d1 += __shfl_down_sync(0xffffffffu, d1, o);
    }
    if (lane == 0) {
        float l0 = g_fm[b * 2 + 0] + b3[0] + d0;
        float l1 = g_fm[b * 2 + 1] + b3[1] + d1;
        float m  = fmaxf(l0, l1);
        float e0 = expf(l0 - m), e1 = expf(l1 - m);
        float inv = 1.0f / (e0 + e1);
        out[b * 2 + 0] = e0 * inv;
        out[b * 2 + 1] = e1 * inv;
    }
}

// ---------------------------------------------------------------------------
extern "C" void kernel_launch(void* const* d_in, const int* in_sizes, int n_in,
                              void* d_out, int out_size)
{
    const int*   uid        = (const int*)  d_in[0];
    const int*   hour       = (const int*)  d_in[1];
    const float* visual     = (const float*)d_in[2];
    const float* scale      = (const float*)d_in[3];
    const int*   gender     = (const int*)  d_in[4];
    const int*   age        = (const int*)  d_in[5];
    const int*   attribute  = (const int*)  d_in[6];
    const float* user_emb   = (const float*)d_in[7];
    const float* hour_emb   = (const float*)d_in[8];
    const float* gender_emb = (const float*)d_in[9];
    const float* age_emb    = (const float*)d_in[10];
    const float* attr_emb   = (const float*)d_in[11];
    const float* visu_w     = (const float*)d_in[12];
    const float* visu_b     = (const float*)d_in[13];
    const float* fm_w       = (const float*)d_in[14];
    const float* fm_b       = (const float*)d_in[15];
    const float* w1         = (const float*)d_in[16];
    const float* b1         = (const float*)d_in[17];
    const float* w2         = (const float*)d_in[18];
    const float* b2         = (const float*)d_in[19];
    const float* w3         = (const float*)d_in[20];
    const float* b3         = (const float*)d_in[21];
    float* out = (float*)d_out;

    __nv_bfloat16 *xhp, *h1p, *h2p, *w1p, *w2p;
    cudaGetSymbolAddress((void**)&xhp, g_xh);
    cudaGetSymbolAddress((void**)&h1p, g_h1h);
    cudaGetSymbolAddress((void**)&h2p, g_h2h);
    cudaGetSymbolAddress((void**)&w1p, g_w1h);
    cudaGetSymbolAddress((void**)&w2p, g_w2h);

    const int SM_TF = 2 * (64 + 64) * 36 * 4;            // 36,864 B
    const int SM_BF = 2 * (128 + 128) * 20 * 4;          // 40,960 B
    cudaFuncSetAttribute(gemm_tf32<64, 64>,   cudaFuncAttributeMaxDynamicSharedMemorySize, SM_TF);
    cudaFuncSetAttribute(gemm_bf16k<128, 128>, cudaFuncAttributeMaxDynamicSharedMemorySize, SM_BF);

    // 0) weight conversion (458752 floats / 4 per thread / 256 per block)
    conv_w_kernel<<<448, 256>>>(w1, w2);

    // 1) embeddings + FM (writes g_xh[:, 0:320] and g_fm)
    embed_fm_kernel<<<BATCH / 4, 256>>>(uid, hour, scale, gender, age, attribute,
                                        user_emb, hour_emb, gender_emb, age_emb,
                                        attr_emb, fm_w, fm_b);

    // 2) vis = visual @ visu_w^T + visu_b -> bf16 g_xh[:, 320:384] (256 CTAs)
    gemm_tf32<64, 64><<<dim3(1, BATCH / 64), 256, SM_TF>>>(
        visual, VISD, visu_w, visu_b, xhp, 384, 320, VISD);

    // 3) h1 = relu(x @ w1^T + b1)   bf16 (512 CTAs)
    gemm_bf16k<128, 128><<<dim3(HID / 128, BATCH / 128), 256, SM_BF>>>(
        xhp, 384, w1p, b1, h1p, HID, 384, 1);

    // 4) h2 = relu(h1 @ w2^T + b2)  bf16 (512 CTAs)
    gemm_bf16k<128, 128><<<dim3(HID / 128, BATCH / 128), 256, SM_BF>>>(
        h1p, HID, w2p, b2, h2p, HID, HID, 1);

    // 5) logits + softmax
    final_kernel<<<BATCH / 8, 256>>>(w3, b3, out);
}